// round 14
// baseline (speedup 1.0000x reference)
#include <cuda_runtime.h>
#include <cuda_fp16.h>
#include <cstdint>

// VQ quantizer: fp16 hi-only HMMA screen + packed-key top-3 + exact rescue.
// R14: 64 rows/warp (4 m-tiles) -> B ldmatrix wavefronts per token halved
// again (4 LDSM.x4 : 32 MMA per chunk). L1 (50%, the binding resource) is
// the target. Single B buffer (R13 showed double-buffering ~free at 16
// warps/SM) pays the A-fragment register bill. 512 tokens/CTA, grid 1024.
//
// Screen: dot_hi = <z_hi,c_hi> via mma.sync. Key: dist''=(||c||^2+256)-2*dot
// (>0 -> uint-orderable); key=(bits&~511)|k; pair-insert top-3 (8 IMNMX/2).
// Rescue (DELTA=0.3): top-2 gap < DELTA -> per-lane exact fp32 rescore;
// top-3 gap < DELTA -> warp-cooperative full exact scan (ballot).
// Exact path: plain ||c||^2, fp32 fmaf, strict <, first-index ties
// (R5/R8/R10-R13 validated, rel_err=0.0).

#define DQ        64
#define KC        512
#define ROWB      144                       // hi fp16 row: 128B data + 16B pad
#define PACK_BYTES (KC * ROWB)              // 73728
#define SM_NRM    PACK_BYTES                // plain ||c||^2 (exact path)
#define SM_NRMK   (SM_NRM + KC * 4)         // ||c||^2 + OFFS (screen keys)
#define SMEM_TOTAL (SM_NRMK + KC * 4)       // 77824
#define THREADS   256
#define MROWS     512                       // 8 warps x 64 rows
#define NCHUNK    (KC / 16)                 // 32
#define DELTA     0.3f
#define OFFS      256.0f

__device__ __align__(16) unsigned char g_cbpack[PACK_BYTES];
__device__ float g_cnorm[KC];               // plain ||c||^2 (NO offset)

// ---------------- helpers ----------------

__device__ __forceinline__ uint32_t smem_u32(const void* p) {
    uint32_t a;
    asm("{ .reg .u64 t; cvta.to.shared.u64 t, %1; cvt.u32.u64 %0, t; }" : "=r"(a) : "l"(p));
    return a;
}

__device__ __forceinline__ uint32_t pack2(__half a, __half b) {
    __half2 h = __halves2half2(a, b);
    return *reinterpret_cast<uint32_t*>(&h);
}

#define LDSM4(r0, r1, r2, r3, addr)                                         \
    asm volatile("ldmatrix.sync.aligned.m8n8.x4.shared.b16 {%0,%1,%2,%3}, [%4];" \
        : "=r"(r0), "=r"(r1), "=r"(r2), "=r"(r3) : "r"(addr))

#define MMA16816(c0, c1, c2, c3, a0, a1, a2, a3, b0, b1)                    \
    asm volatile("mma.sync.aligned.m16n8k16.row.col.f32.f16.f16.f32 "       \
        "{%0,%1,%2,%3}, {%4,%5,%6,%7}, {%8,%9}, {%0,%1,%2,%3};"             \
        : "+f"(c0), "+f"(c1), "+f"(c2), "+f"(c3)                            \
        : "r"(a0), "r"(a1), "r"(a2), "r"(a3), "r"(b0), "r"(b1))

// Single sorted top-3 insert (a<=b<=c), 5 IMNMX (warp merges only).
__device__ __forceinline__ void ins3(uint32_t& a, uint32_t& b, uint32_t& c,
                                     uint32_t x) {
    uint32_t h1 = max(a, x); a = min(a, x);
    uint32_t h2 = max(b, h1); b = min(b, h1);
    c = min(c, h2);
}

// Pair insert: merge sorted pair {x,y} into sorted (a<=b<=c). 8 IMNMX.
__device__ __forceinline__ void ins3p(uint32_t& a, uint32_t& b, uint32_t& c,
                                      uint32_t x, uint32_t y) {
    uint32_t mn = min(x, y), mx = max(x, y);
    uint32_t u = max(a, mn); a = min(a, mn);
    uint32_t v = min(b, mx);
    uint32_t w = max(u, v);  b = min(u, v);
    c = min(c, w);
}

// Screen key ONLY (nrmk already carries +OFFS). Never used in exact path.
__device__ __forceinline__ uint32_t mkkey(float dot, float nrmk, int k) {
    const float d = fmaf(-2.0f, dot, nrmk);
    return (__float_as_uint(d) & ~511u) | (uint32_t)k;
}

// R5 bit-exact offsetless distance (fp32, fixed fmaf order).
__device__ __forceinline__ float exact_dist(const float4* zv, const float* crow_f,
                                            float nrm) {
    const float4* crow = reinterpret_cast<const float4*>(crow_f);
    float s0 = 0.f, s1 = 0.f, s2 = 0.f, s3 = 0.f;
    #pragma unroll
    for (int i = 0; i < 16; i++) {
        float4 c = crow[i]; float4 z = zv[i];
        s0 = fmaf(z.x, c.x, s0); s1 = fmaf(z.y, c.y, s1);
        s2 = fmaf(z.z, c.z, s2); s3 = fmaf(z.w, c.w, s3);
    }
    return fmaf(-2.0f, (s0 + s1) + (s2 + s3), nrm);
}

// ---------------- prep ----------------

__global__ void prep_kernel(const float* __restrict__ cb) {
    const int k = threadIdx.x;
    if (k >= KC) return;
    const float4* row = reinterpret_cast<const float4*>(cb + (size_t)k * DQ);
    uint32_t* dst = reinterpret_cast<uint32_t*>(g_cbpack + (size_t)k * ROWB);
    float s0 = 0.f, s1 = 0.f, s2 = 0.f, s3 = 0.f;
    #pragma unroll
    for (int i = 0; i < 16; i++) {
        float4 f = row[i];
        s0 = fmaf(f.x, f.x, s0); s1 = fmaf(f.y, f.y, s1);
        s2 = fmaf(f.z, f.z, s2); s3 = fmaf(f.w, f.w, s3);
        dst[2*i]     = pack2(__float2half_rn(f.x), __float2half_rn(f.y));
        dst[2*i + 1] = pack2(__float2half_rn(f.z), __float2half_rn(f.w));
    }
    g_cnorm[k] = (s0 + s1) + (s2 + s3);     // plain (R5 semantics)
}

// ---------------- main ----------------

__global__ __launch_bounds__(THREADS, 2)
void vq_main(const float* __restrict__ ze,
             const float* __restrict__ cb,
             float* __restrict__ out) {
    extern __shared__ char smem[];
    float* snrm  = reinterpret_cast<float*>(smem + SM_NRM);
    float* snrmk = reinterpret_cast<float*>(smem + SM_NRMK);

    // Cooperative copy: hi-pack + norms (+offset copy) -> SMEM (~78 KB).
    {
        const uint4* s0 = reinterpret_cast<const uint4*>(g_cbpack);
        uint4* d0 = reinterpret_cast<uint4*>(smem);
        for (int i = threadIdx.x; i < PACK_BYTES / 16; i += THREADS) d0[i] = s0[i];
        for (int i = threadIdx.x; i < KC; i += THREADS) {
            const float n = g_cnorm[i];
            snrm[i]  = n;
            snrmk[i] = n + OFFS;
        }
    }

    const int tid  = threadIdx.x;
    const int w    = tid >> 5;              // 0..7
    const int lane = tid & 31;
    const int g    = lane >> 2;
    const int t    = lane & 3;
    const int row_base = blockIdx.x * MROWS + w * 64;   // warp covers 64 rows

    // A fragments (hi only), 4 m-tiles: Ah[mt][kt][2*h + rr]
    uint32_t Ah[4][4][4];
    #pragma unroll
    for (int mt = 0; mt < 4; mt++)
        #pragma unroll
        for (int kt = 0; kt < 4; kt++)
            #pragma unroll
            for (int h = 0; h < 2; h++)
                #pragma unroll
                for (int rr = 0; rr < 2; rr++) {
                    const int row = row_base + mt * 16 + g + 8 * rr;
                    const int col = kt * 16 + h * 8 + 2 * t;
                    float2 f = *reinterpret_cast<const float2*>(ze + (size_t)row * DQ + col);
                    Ah[mt][kt][2*h + rr] = pack2(__float2half_rn(f.x), __float2half_rn(f.y));
                }
    __syncthreads();

    // Sorted top-3 keys per row slot. slot s = 2*mt + rr -> row (s>>1)*16 + g + 8*(s&1).
    uint32_t K1[8], K2[8], K3[8];
    #pragma unroll
    for (int s = 0; s < 8; s++) { K1[s] = K2[s] = K3[s] = 0xFFFFFFFFu; }

    const uint32_t smem_u = smem_u32(smem);
    const int      brow = ((lane >> 4) & 1) * 8 + (lane & 7);
    const uint32_t koff = ((lane >> 3) & 1) * 16;
    const uint32_t bwarp = smem_u + (uint32_t)brow * ROWB + koff;

    #pragma unroll 1
    for (int c = 0; c < NCHUNK; c++) {
        const int n0 = c * 16;
        const uint32_t bbase = bwarp + (uint32_t)(n0 * ROWB);

        uint32_t B[4][4];
        #pragma unroll
        for (int kt = 0; kt < 4; kt++)
            LDSM4(B[kt][0], B[kt][1], B[kt][2], B[kt][3], bbase + kt * 32);

        const float2 ck0 = *reinterpret_cast<const float2*>(&snrmk[n0 + 2 * t]);
        const float2 ck1 = *reinterpret_cast<const float2*>(&snrmk[n0 + 8 + 2 * t]);

        // mt-split: 8 MMAs then that m-tile's epilogue (alu overlaps tensor).
        #pragma unroll
        for (int mt = 0; mt < 4; mt++) {
            float acc[2][4];
            #pragma unroll
            for (int nt = 0; nt < 2; nt++)
                #pragma unroll
                for (int q = 0; q < 4; q++) acc[nt][q] = 0.f;

            #pragma unroll
            for (int kt = 0; kt < 4; kt++) {
                MMA16816(acc[0][0], acc[0][1], acc[0][2], acc[0][3],
                         Ah[mt][kt][0], Ah[mt][kt][1], Ah[mt][kt][2], Ah[mt][kt][3],
                         B[kt][0], B[kt][1]);
                MMA16816(acc[1][0], acc[1][1], acc[1][2], acc[1][3],
                         Ah[mt][kt][0], Ah[mt][kt][1], Ah[mt][kt][2], Ah[mt][kt][3],
                         B[kt][2], B[kt][3]);
            }

            const int sA = 2 * mt, sB = 2 * mt + 1;
            #pragma unroll
            for (int nt = 0; nt < 2; nt++) {
                const float cA = nt ? ck1.x : ck0.x;
                const float cB = nt ? ck1.y : ck0.y;
                const int colA = n0 + nt * 8 + 2 * t;
                ins3p(K1[sA], K2[sA], K3[sA],
                      mkkey(acc[nt][0], cA, colA),
                      mkkey(acc[nt][1], cB, colA + 1));
                ins3p(K1[sB], K2[sB], K3[sB],
                      mkkey(acc[nt][2], cA, colA),
                      mkkey(acc[nt][3], cB, colA + 1));
            }
        }
    }

    // Cross-lane merge (lanes 4g..4g+3 share the same 8 rows).
    #pragma unroll
    for (int xo = 1; xo <= 2; xo <<= 1) {
        #pragma unroll
        for (int s = 0; s < 8; s++) {
            uint32_t o1 = __shfl_xor_sync(0xFFFFFFFFu, K1[s], xo);
            uint32_t o2 = __shfl_xor_sync(0xFFFFFFFFu, K2[s], xo);
            uint32_t o3 = __shfl_xor_sync(0xFFFFFFFFu, K3[s], xo);
            ins3p(K1[s], K2[s], K3[s], o1, o2);
            ins3(K1[s], K2[s], K3[s], o3);
        }
    }

    // ---- Resolution: lane 4g+t owns slots t and t+4. ----
    int kw[2];
    #pragma unroll
    for (int si = 0; si < 2; si++) {
        const int s = t + 4 * si;
        const int my_row = row_base + (s >> 1) * 16 + g + 8 * (s & 1);
        const uint32_t key1 = K1[s], key2 = K2[s], key3 = K3[s];
        const int rk1 = (int)(key1 & 511u), rk2 = (int)(key2 & 511u);
        const float a1 = __uint_as_float(key1 & ~511u);
        const float a2 = __uint_as_float(key2 & ~511u);
        const float a3 = __uint_as_float(key3 & ~511u);
        kw[si] = rk1;
        const bool need_full = (a3 - a1 < DELTA);
        const bool need_pair = !need_full && (a2 - a1 < DELTA);

        // Warp-cooperative full exact scans (rare; ~0.12% of tokens).
        unsigned fmask = __ballot_sync(0xFFFFFFFFu, need_full);
        while (fmask) {
            const int src = __ffs(fmask) - 1;
            fmask &= fmask - 1;
            const int ss = (src & 3) + 4 * si, sgg = src >> 2;
            const int srow = row_base + (ss >> 1) * 16 + sgg + 8 * (ss & 1);
            float4 zv[16];
            const float4* zp = reinterpret_cast<const float4*>(ze + (size_t)srow * DQ);
            #pragma unroll
            for (int i = 0; i < 16; i++) zv[i] = zp[i];
            float bd = 3.4e38f; int bk = 0;
            const int k0 = lane * 16;
            #pragma unroll 1
            for (int q = 0; q < 16; q++) {
                const int k = k0 + q;
                const float d = exact_dist(zv, cb + (size_t)k * DQ, snrm[k]);
                if (d < bd) { bd = d; bk = k; }
            }
            #pragma unroll
            for (int xo = 16; xo >= 1; xo >>= 1) {
                const float od = __shfl_xor_sync(0xFFFFFFFFu, bd, xo);
                const int   ok = __shfl_xor_sync(0xFFFFFFFFu, bk, xo);
                if (od < bd || (od == bd && ok < bk)) { bd = od; bk = ok; }
            }
            if (lane == src) kw[si] = bk;
        }

        // Per-lane pairwise exact rescore (~5% of tokens).
        if (need_pair) {
            float4 zv[16];
            const float4* zp = reinterpret_cast<const float4*>(ze + (size_t)my_row * DQ);
            #pragma unroll
            for (int i = 0; i < 16; i++) zv[i] = zp[i];
            const float e1 = exact_dist(zv, cb + (size_t)rk1 * DQ, snrm[rk1]);
            const float e2 = exact_dist(zv, cb + (size_t)rk2 * DQ, snrm[rk2]);
            if (e2 < e1 || (e2 == e1 && rk2 < rk1)) kw[si] = rk2;
        }
    }

    // Coalesced gather (cb is L2-resident) + write: warp streams its 64 rows.
    // Row r: slot s = 2*(r>>4) + ((r>>3)&1); owner lane = 4*(r&7) + (s&3);
    // value index si = s>>2 (= r>>5).
    #pragma unroll 1
    for (int r = 0; r < 64; r++) {
        const int s = 2 * (r >> 4) + ((r >> 3) & 1);
        const int src_lane = 4 * (r & 7) + (s & 3);
        const int kk = __shfl_sync(0xFFFFFFFFu, (r < 32) ? kw[0] : kw[1], src_lane);
        const float2 v = reinterpret_cast<const float2*>(cb + (size_t)kk * DQ)[lane];
        reinterpret_cast<float2*>(out + (size_t)(row_base + r) * DQ)[lane] = v;
    }
}

extern "C" void kernel_launch(void* const* d_in, const int* in_sizes, int n_in,
                              void* d_out, int out_size) {
    const float* ze = (const float*)d_in[0];
    const float* cb = (const float*)d_in[1];
    float* out = (float*)d_out;
    const int n_tokens = in_sizes[0] / DQ;
    const int grid = n_tokens / MROWS;   // 1024

    prep_kernel<<<1, KC>>>(cb);
    cudaFuncSetAttribute(vq_main,
                         cudaFuncAttributeMaxDynamicSharedMemorySize, SMEM_TOTAL);
    vq_main<<<grid, THREADS, SMEM_TOTAL>>>(ze, cb, out);
}

// round 15
// speedup vs baseline: 1.0174x; 1.0174x over previous
#include <cuda_runtime.h>
#include <cuda_fp16.h>
#include <cstdint>

// VQ quantizer: fp16 hi-only HMMA screen + packed-key top-3 + exact rescue.
// R15: occupancy push. Issue% has been pinned ~34 across R11-R14 -> warp-
// starved at 16 warps/SM (regfile cap at 128 regs). Changes:
//  (1) SMEM 77824 -> 75776 (drop snrmk; +OFFS folded per chunk, 4 FADDs)
//      so 3 CTAs x 75776 = 227328 <= 228KB/SM.
//  (2) __launch_bounds__(256,3): regs capped ~85 -> 24 warps/SM (+50%).
//  (3) Gather tail: batch 4 LDGs before 4 STGs (MLP=4, was serial).
// 32 rows/warp (R13 geometry, grid 2048 -> 4.5 waves of 456).
//
// Screen: dot_hi = <z_hi,c_hi> via mma.sync. Key: dist''=(||c||^2+256)-2*dot
// (>0 -> uint-orderable); key=(bits&~511)|k; pair-insert top-3 (8 IMNMX/2).
// Rescue (DELTA=0.3): top-2 gap < DELTA -> per-lane exact fp32 rescore;
// top-3 gap < DELTA -> warp-cooperative full exact scan (ballot).
// Exact path: plain ||c||^2, fp32 fmaf, strict <, first-index ties
// (R5/R8/R10-R14 validated, rel_err=0.0).

#define DQ        64
#define KC        512
#define ROWB      144                       // hi fp16 row: 128B data + 16B pad
#define PACK_BYTES (KC * ROWB)              // 73728
#define SM_NRM    PACK_BYTES                // plain ||c||^2 (exact path + keys)
#define SMEM_TOTAL (SM_NRM + KC * 4)        // 75776
#define THREADS   256
#define MROWS     256                       // 8 warps x 32 rows
#define NCHUNK    (KC / 16)                 // 32
#define DELTA     0.3f
#define OFFS      256.0f

__device__ __align__(16) unsigned char g_cbpack[PACK_BYTES];
__device__ float g_cnorm[KC];               // plain ||c||^2 (NO offset)

// ---------------- helpers ----------------

__device__ __forceinline__ uint32_t smem_u32(const void* p) {
    uint32_t a;
    asm("{ .reg .u64 t; cvta.to.shared.u64 t, %1; cvt.u32.u64 %0, t; }" : "=r"(a) : "l"(p));
    return a;
}

__device__ __forceinline__ uint32_t pack2(__half a, __half b) {
    __half2 h = __halves2half2(a, b);
    return *reinterpret_cast<uint32_t*>(&h);
}

#define LDSM4(r0, r1, r2, r3, addr)                                         \
    asm volatile("ldmatrix.sync.aligned.m8n8.x4.shared.b16 {%0,%1,%2,%3}, [%4];" \
        : "=r"(r0), "=r"(r1), "=r"(r2), "=r"(r3) : "r"(addr))

#define MMA16816(c0, c1, c2, c3, a0, a1, a2, a3, b0, b1)                    \
    asm volatile("mma.sync.aligned.m16n8k16.row.col.f32.f16.f16.f32 "       \
        "{%0,%1,%2,%3}, {%4,%5,%6,%7}, {%8,%9}, {%0,%1,%2,%3};"             \
        : "+f"(c0), "+f"(c1), "+f"(c2), "+f"(c3)                            \
        : "r"(a0), "r"(a1), "r"(a2), "r"(a3), "r"(b0), "r"(b1))

// Single sorted top-3 insert (a<=b<=c), 5 IMNMX (warp merges only).
__device__ __forceinline__ void ins3(uint32_t& a, uint32_t& b, uint32_t& c,
                                     uint32_t x) {
    uint32_t h1 = max(a, x); a = min(a, x);
    uint32_t h2 = max(b, h1); b = min(b, h1);
    c = min(c, h2);
}

// Pair insert: merge sorted pair {x,y} into sorted (a<=b<=c). 8 IMNMX.
__device__ __forceinline__ void ins3p(uint32_t& a, uint32_t& b, uint32_t& c,
                                      uint32_t x, uint32_t y) {
    uint32_t mn = min(x, y), mx = max(x, y);
    uint32_t u = max(a, mn); a = min(a, mn);
    uint32_t v = min(b, mx);
    uint32_t w = max(u, v);  b = min(u, v);
    c = min(c, w);
}

// Screen key ONLY (nrmk carries +OFFS, added per chunk). Not the exact path.
__device__ __forceinline__ uint32_t mkkey(float dot, float nrmk, int k) {
    const float d = fmaf(-2.0f, dot, nrmk);
    return (__float_as_uint(d) & ~511u) | (uint32_t)k;
}

// R5 bit-exact offsetless distance (fp32, fixed fmaf order).
__device__ __forceinline__ float exact_dist(const float4* zv, const float* crow_f,
                                            float nrm) {
    const float4* crow = reinterpret_cast<const float4*>(crow_f);
    float s0 = 0.f, s1 = 0.f, s2 = 0.f, s3 = 0.f;
    #pragma unroll
    for (int i = 0; i < 16; i++) {
        float4 c = crow[i]; float4 z = zv[i];
        s0 = fmaf(z.x, c.x, s0); s1 = fmaf(z.y, c.y, s1);
        s2 = fmaf(z.z, c.z, s2); s3 = fmaf(z.w, c.w, s3);
    }
    return fmaf(-2.0f, (s0 + s1) + (s2 + s3), nrm);
}

// ---------------- prep ----------------

__global__ void prep_kernel(const float* __restrict__ cb) {
    const int k = threadIdx.x;
    if (k >= KC) return;
    const float4* row = reinterpret_cast<const float4*>(cb + (size_t)k * DQ);
    uint32_t* dst = reinterpret_cast<uint32_t*>(g_cbpack + (size_t)k * ROWB);
    float s0 = 0.f, s1 = 0.f, s2 = 0.f, s3 = 0.f;
    #pragma unroll
    for (int i = 0; i < 16; i++) {
        float4 f = row[i];
        s0 = fmaf(f.x, f.x, s0); s1 = fmaf(f.y, f.y, s1);
        s2 = fmaf(f.z, f.z, s2); s3 = fmaf(f.w, f.w, s3);
        dst[2*i]     = pack2(__float2half_rn(f.x), __float2half_rn(f.y));
        dst[2*i + 1] = pack2(__float2half_rn(f.z), __float2half_rn(f.w));
    }
    g_cnorm[k] = (s0 + s1) + (s2 + s3);     // plain (R5 semantics)
}

// ---------------- main ----------------

__global__ __launch_bounds__(THREADS, 3)
void vq_main(const float* __restrict__ ze,
             const float* __restrict__ cb,
             float* __restrict__ out) {
    extern __shared__ char smem[];
    float* snrm = reinterpret_cast<float*>(smem + SM_NRM);

    // Cooperative copy: hi-pack + norms -> SMEM (74 KB).
    {
        const uint4* s0 = reinterpret_cast<const uint4*>(g_cbpack);
        uint4* d0 = reinterpret_cast<uint4*>(smem);
        for (int i = threadIdx.x; i < PACK_BYTES / 16; i += THREADS) d0[i] = s0[i];
        for (int i = threadIdx.x; i < KC; i += THREADS) snrm[i] = g_cnorm[i];
    }

    const int tid  = threadIdx.x;
    const int w    = tid >> 5;              // 0..7
    const int lane = tid & 31;
    const int g    = lane >> 2;
    const int t    = lane & 3;
    const int row_base = blockIdx.x * MROWS + w * 32;   // warp covers 32 rows

    // A fragments (hi only), 2 m-tiles: Ah[mt][kt][2*h + rr]
    uint32_t Ah[2][4][4];
    #pragma unroll
    for (int mt = 0; mt < 2; mt++)
        #pragma unroll
        for (int kt = 0; kt < 4; kt++)
            #pragma unroll
            for (int h = 0; h < 2; h++)
                #pragma unroll
                for (int rr = 0; rr < 2; rr++) {
                    const int row = row_base + mt * 16 + g + 8 * rr;
                    const int col = kt * 16 + h * 8 + 2 * t;
                    float2 f = *reinterpret_cast<const float2*>(ze + (size_t)row * DQ + col);
                    Ah[mt][kt][2*h + rr] = pack2(__float2half_rn(f.x), __float2half_rn(f.y));
                }
    __syncthreads();

    // Sorted top-3 keys per row slot. slot s = 2*mt + rr -> row (s>>1)*16 + g + 8*(s&1).
    uint32_t K1[4], K2[4], K3[4];
    #pragma unroll
    for (int s = 0; s < 4; s++) { K1[s] = K2[s] = K3[s] = 0xFFFFFFFFu; }

    const uint32_t smem_u = smem_u32(smem);
    const int      brow = ((lane >> 4) & 1) * 8 + (lane & 7);
    const uint32_t koff = ((lane >> 3) & 1) * 16;
    const uint32_t bwarp = smem_u + (uint32_t)brow * ROWB + koff;

    #pragma unroll 1
    for (int c = 0; c < NCHUNK; c++) {
        const int n0 = c * 16;
        const uint32_t bbase = bwarp + (uint32_t)(n0 * ROWB);

        uint32_t B[4][4];
        #pragma unroll
        for (int kt = 0; kt < 4; kt++)
            LDSM4(B[kt][0], B[kt][1], B[kt][2], B[kt][3], bbase + kt * 32);

        // Per-chunk key norms: plain snrm + OFFS (bit-identical to stored copy).
        const float2 c0f = *reinterpret_cast<const float2*>(&snrm[n0 + 2 * t]);
        const float2 c1f = *reinterpret_cast<const float2*>(&snrm[n0 + 8 + 2 * t]);
        const float ck0x = c0f.x + OFFS, ck0y = c0f.y + OFFS;
        const float ck1x = c1f.x + OFFS, ck1y = c1f.y + OFFS;

        // mt-split: 8 MMAs then that m-tile's epilogue (alu overlaps tensor).
        #pragma unroll
        for (int mt = 0; mt < 2; mt++) {
            float acc[2][4];
            #pragma unroll
            for (int nt = 0; nt < 2; nt++)
                #pragma unroll
                for (int q = 0; q < 4; q++) acc[nt][q] = 0.f;

            #pragma unroll
            for (int kt = 0; kt < 4; kt++) {
                MMA16816(acc[0][0], acc[0][1], acc[0][2], acc[0][3],
                         Ah[mt][kt][0], Ah[mt][kt][1], Ah[mt][kt][2], Ah[mt][kt][3],
                         B[kt][0], B[kt][1]);
                MMA16816(acc[1][0], acc[1][1], acc[1][2], acc[1][3],
                         Ah[mt][kt][0], Ah[mt][kt][1], Ah[mt][kt][2], Ah[mt][kt][3],
                         B[kt][2], B[kt][3]);
            }

            const int sA = 2 * mt, sB = 2 * mt + 1;
            #pragma unroll
            for (int nt = 0; nt < 2; nt++) {
                const float cA = nt ? ck1x : ck0x;
                const float cB = nt ? ck1y : ck0y;
                const int colA = n0 + nt * 8 + 2 * t;
                ins3p(K1[sA], K2[sA], K3[sA],
                      mkkey(acc[nt][0], cA, colA),
                      mkkey(acc[nt][1], cB, colA + 1));
                ins3p(K1[sB], K2[sB], K3[sB],
                      mkkey(acc[nt][2], cA, colA),
                      mkkey(acc[nt][3], cB, colA + 1));
            }
        }
    }

    // Cross-lane merge (lanes 4g..4g+3 share the same 4 rows).
    #pragma unroll
    for (int xo = 1; xo <= 2; xo <<= 1) {
        #pragma unroll
        for (int s = 0; s < 4; s++) {
            uint32_t o1 = __shfl_xor_sync(0xFFFFFFFFu, K1[s], xo);
            uint32_t o2 = __shfl_xor_sync(0xFFFFFFFFu, K2[s], xo);
            uint32_t o3 = __shfl_xor_sync(0xFFFFFFFFu, K3[s], xo);
            ins3p(K1[s], K2[s], K3[s], o1, o2);
            ins3(K1[s], K2[s], K3[s], o3);
        }
    }

    // ---- Resolution: lane 4g+t owns slot t -> row (t>>1)*16 + g + 8*(t&1). ----
    const int my_row = row_base + (t >> 1) * 16 + g + 8 * (t & 1);
    const uint32_t key1 = K1[t], key2 = K2[t], key3 = K3[t];
    const int rk1 = (int)(key1 & 511u), rk2 = (int)(key2 & 511u);
    const float a1 = __uint_as_float(key1 & ~511u);
    const float a2 = __uint_as_float(key2 & ~511u);
    const float a3 = __uint_as_float(key3 & ~511u);
    int  kw = rk1;
    const bool need_full = (a3 - a1 < DELTA);
    const bool need_pair = !need_full && (a2 - a1 < DELTA);

    // Warp-cooperative full exact scans (rare; ~0.12% of tokens).
    unsigned fmask = __ballot_sync(0xFFFFFFFFu, need_full);
    while (fmask) {
        const int src = __ffs(fmask) - 1;
        fmask &= fmask - 1;
        const int stt = src & 3, sgg = src >> 2;
        const int srow = row_base + (stt >> 1) * 16 + sgg + 8 * (stt & 1);
        float4 zv[16];
        const float4* zp = reinterpret_cast<const float4*>(ze + (size_t)srow * DQ);
        #pragma unroll
        for (int i = 0; i < 16; i++) zv[i] = zp[i];
        float bd = 3.4e38f; int bk = 0;
        const int k0 = lane * 16;
        #pragma unroll 1
        for (int q = 0; q < 16; q++) {
            const int k = k0 + q;
            const float d = exact_dist(zv, cb + (size_t)k * DQ, snrm[k]);
            if (d < bd) { bd = d; bk = k; }
        }
        #pragma unroll
        for (int xo = 16; xo >= 1; xo >>= 1) {
            const float od = __shfl_xor_sync(0xFFFFFFFFu, bd, xo);
            const int   ok = __shfl_xor_sync(0xFFFFFFFFu, bk, xo);
            if (od < bd || (od == bd && ok < bk)) { bd = od; bk = ok; }
        }
        if (lane == src) kw = bk;
    }

    // Per-lane pairwise exact rescore (~5% of tokens).
    if (need_pair) {
        float4 zv[16];
        const float4* zp = reinterpret_cast<const float4*>(ze + (size_t)my_row * DQ);
        #pragma unroll
        for (int i = 0; i < 16; i++) zv[i] = zp[i];
        const float e1 = exact_dist(zv, cb + (size_t)rk1 * DQ, snrm[rk1]);
        const float e2 = exact_dist(zv, cb + (size_t)rk2 * DQ, snrm[rk2]);
        if (e2 < e1 || (e2 == e1 && rk2 < rk1)) kw = rk2;
    }

    // Coalesced gather (cb is L2-resident) + write, batched 4-deep (MLP=4).
    #pragma unroll 1
    for (int r0 = 0; r0 < 32; r0 += 4) {
        float2 v[4];
        #pragma unroll
        for (int j = 0; j < 4; j++) {
            const int r = r0 + j;
            const int mt = r >> 4, rr = (r >> 3) & 1, gg = r & 7;
            const int src_lane = 4 * gg + 2 * mt + rr;
            const int kk = __shfl_sync(0xFFFFFFFFu, kw, src_lane);
            v[j] = reinterpret_cast<const float2*>(cb + (size_t)kk * DQ)[lane];
        }
        #pragma unroll
        for (int j = 0; j < 4; j++)
            reinterpret_cast<float2*>(out + (size_t)(row_base + r0 + j) * DQ)[lane] = v[j];
    }
}

extern "C" void kernel_launch(void* const* d_in, const int* in_sizes, int n_in,
                              void* d_out, int out_size) {
    const float* ze = (const float*)d_in[0];
    const float* cb = (const float*)d_in[1];
    float* out = (float*)d_out;
    const int n_tokens = in_sizes[0] / DQ;
    const int grid = n_tokens / MROWS;   // 2048

    prep_kernel<<<1, KC>>>(cb);
    cudaFuncSetAttribute(vq_main,
                         cudaFuncAttributeMaxDynamicSharedMemorySize, SMEM_TOTAL);
    vq_main<<<grid, THREADS, SMEM_TOTAL>>>(ze, cb, out);
}

// round 16
// speedup vs baseline: 1.0682x; 1.0500x over previous
#include <cuda_runtime.h>
#include <cuda_fp16.h>
#include <cstdint>

// VQ quantizer: fp16 hi-only HMMA screen + packed-key top-3 + exact rescue.
// R16: PERSISTENT CTAs. grid = 444 (3 CTAs/SM x 148); each CTA strides over
// ~4-5 token tiles. The 74KB codebook SMEM copy happens ONCE per CTA
// (was once per tile: 2048 x 74KB = 151MB of L2/DRAM traffic ~ 600GB/s of
// the measured 891) and the 4.61-wave quantization tail collapses.
// Mainloop body identical to R15 (validated rel_err=0.0).
//
// Screen: dot_hi = <z_hi,c_hi> via mma.sync. Key: dist''=(||c||^2+256)-2*dot
// (>0 -> uint-orderable); key=(bits&~511)|k; pair-insert top-3 (8 IMNMX/2).
// Rescue (DELTA=0.3): top-2 gap < DELTA -> per-lane exact fp32 rescore;
// top-3 gap < DELTA -> warp-cooperative full exact scan (ballot).
// Exact path: plain ||c||^2, fp32 fmaf, strict <, first-index ties.

#define DQ        64
#define KC        512
#define ROWB      144                       // hi fp16 row: 128B data + 16B pad
#define PACK_BYTES (KC * ROWB)              // 73728
#define SM_NRM    PACK_BYTES                // plain ||c||^2 (exact path + keys)
#define SMEM_TOTAL (SM_NRM + KC * 4)        // 75776
#define THREADS   256
#define MROWS     256                       // 8 warps x 32 rows per tile
#define NCHUNK    (KC / 16)                 // 32
#define NSM       148
#define CTAS      (3 * NSM)                 // 444 persistent CTAs
#define DELTA     0.3f
#define OFFS      256.0f

__device__ __align__(16) unsigned char g_cbpack[PACK_BYTES];
__device__ float g_cnorm[KC];               // plain ||c||^2 (NO offset)

// ---------------- helpers ----------------

__device__ __forceinline__ uint32_t smem_u32(const void* p) {
    uint32_t a;
    asm("{ .reg .u64 t; cvta.to.shared.u64 t, %1; cvt.u32.u64 %0, t; }" : "=r"(a) : "l"(p));
    return a;
}

__device__ __forceinline__ uint32_t pack2(__half a, __half b) {
    __half2 h = __halves2half2(a, b);
    return *reinterpret_cast<uint32_t*>(&h);
}

#define LDSM4(r0, r1, r2, r3, addr)                                         \
    asm volatile("ldmatrix.sync.aligned.m8n8.x4.shared.b16 {%0,%1,%2,%3}, [%4];" \
        : "=r"(r0), "=r"(r1), "=r"(r2), "=r"(r3) : "r"(addr))

#define MMA16816(c0, c1, c2, c3, a0, a1, a2, a3, b0, b1)                    \
    asm volatile("mma.sync.aligned.m16n8k16.row.col.f32.f16.f16.f32 "       \
        "{%0,%1,%2,%3}, {%4,%5,%6,%7}, {%8,%9}, {%0,%1,%2,%3};"             \
        : "+f"(c0), "+f"(c1), "+f"(c2), "+f"(c3)                            \
        : "r"(a0), "r"(a1), "r"(a2), "r"(a3), "r"(b0), "r"(b1))

// Single sorted top-3 insert (a<=b<=c), 5 IMNMX (warp merges only).
__device__ __forceinline__ void ins3(uint32_t& a, uint32_t& b, uint32_t& c,
                                     uint32_t x) {
    uint32_t h1 = max(a, x); a = min(a, x);
    uint32_t h2 = max(b, h1); b = min(b, h1);
    c = min(c, h2);
}

// Pair insert: merge sorted pair {x,y} into sorted (a<=b<=c). 8 IMNMX.
__device__ __forceinline__ void ins3p(uint32_t& a, uint32_t& b, uint32_t& c,
                                      uint32_t x, uint32_t y) {
    uint32_t mn = min(x, y), mx = max(x, y);
    uint32_t u = max(a, mn); a = min(a, mn);
    uint32_t v = min(b, mx);
    uint32_t w = max(u, v);  b = min(u, v);
    c = min(c, w);
}

// Screen key ONLY (nrmk carries +OFFS, added per chunk). Not the exact path.
__device__ __forceinline__ uint32_t mkkey(float dot, float nrmk, int k) {
    const float d = fmaf(-2.0f, dot, nrmk);
    return (__float_as_uint(d) & ~511u) | (uint32_t)k;
}

// R5 bit-exact offsetless distance (fp32, fixed fmaf order).
__device__ __forceinline__ float exact_dist(const float4* zv, const float* crow_f,
                                            float nrm) {
    const float4* crow = reinterpret_cast<const float4*>(crow_f);
    float s0 = 0.f, s1 = 0.f, s2 = 0.f, s3 = 0.f;
    #pragma unroll
    for (int i = 0; i < 16; i++) {
        float4 c = crow[i]; float4 z = zv[i];
        s0 = fmaf(z.x, c.x, s0); s1 = fmaf(z.y, c.y, s1);
        s2 = fmaf(z.z, c.z, s2); s3 = fmaf(z.w, c.w, s3);
    }
    return fmaf(-2.0f, (s0 + s1) + (s2 + s3), nrm);
}

// ---------------- prep ----------------

__global__ void prep_kernel(const float* __restrict__ cb) {
    const int k = threadIdx.x;
    if (k >= KC) return;
    const float4* row = reinterpret_cast<const float4*>(cb + (size_t)k * DQ);
    uint32_t* dst = reinterpret_cast<uint32_t*>(g_cbpack + (size_t)k * ROWB);
    float s0 = 0.f, s1 = 0.f, s2 = 0.f, s3 = 0.f;
    #pragma unroll
    for (int i = 0; i < 16; i++) {
        float4 f = row[i];
        s0 = fmaf(f.x, f.x, s0); s1 = fmaf(f.y, f.y, s1);
        s2 = fmaf(f.z, f.z, s2); s3 = fmaf(f.w, f.w, s3);
        dst[2*i]     = pack2(__float2half_rn(f.x), __float2half_rn(f.y));
        dst[2*i + 1] = pack2(__float2half_rn(f.z), __float2half_rn(f.w));
    }
    g_cnorm[k] = (s0 + s1) + (s2 + s3);     // plain (R5 semantics)
}

// ---------------- main (persistent) ----------------

__global__ __launch_bounds__(THREADS, 3)
void vq_main(const float* __restrict__ ze,
             const float* __restrict__ cb,
             float* __restrict__ out,
             int n_tiles) {
    extern __shared__ char smem[];
    float* snrm = reinterpret_cast<float*>(smem + SM_NRM);

    // ONE-TIME cooperative copy: hi-pack + norms -> SMEM (74 KB).
    {
        const uint4* s0 = reinterpret_cast<const uint4*>(g_cbpack);
        uint4* d0 = reinterpret_cast<uint4*>(smem);
        for (int i = threadIdx.x; i < PACK_BYTES / 16; i += THREADS) d0[i] = s0[i];
        for (int i = threadIdx.x; i < KC; i += THREADS) snrm[i] = g_cnorm[i];
    }
    __syncthreads();

    const int tid  = threadIdx.x;
    const int w    = tid >> 5;              // 0..7
    const int lane = tid & 31;
    const int g    = lane >> 2;
    const int t    = lane & 3;

    const uint32_t smem_u = smem_u32(smem);
    const int      brow = ((lane >> 4) & 1) * 8 + (lane & 7);
    const uint32_t koff = ((lane >> 3) & 1) * 16;
    const uint32_t bwarp = smem_u + (uint32_t)brow * ROWB + koff;

    // Persistent tile loop: SMEM is read-only after prolog -> no per-tile sync.
    #pragma unroll 1
    for (int tile = blockIdx.x; tile < n_tiles; tile += CTAS) {
        const int row_base = tile * MROWS + w * 32;     // warp covers 32 rows

        // A fragments (hi only), 2 m-tiles: Ah[mt][kt][2*h + rr]
        uint32_t Ah[2][4][4];
        #pragma unroll
        for (int mt = 0; mt < 2; mt++)
            #pragma unroll
            for (int kt = 0; kt < 4; kt++)
                #pragma unroll
                for (int h = 0; h < 2; h++)
                    #pragma unroll
                    for (int rr = 0; rr < 2; rr++) {
                        const int row = row_base + mt * 16 + g + 8 * rr;
                        const int col = kt * 16 + h * 8 + 2 * t;
                        float2 f = *reinterpret_cast<const float2*>(
                            ze + (size_t)row * DQ + col);
                        Ah[mt][kt][2*h + rr] =
                            pack2(__float2half_rn(f.x), __float2half_rn(f.y));
                    }

        // Sorted top-3 keys per row slot (s=2*mt+rr -> row (s>>1)*16+g+8*(s&1)).
        uint32_t K1[4], K2[4], K3[4];
        #pragma unroll
        for (int s = 0; s < 4; s++) { K1[s] = K2[s] = K3[s] = 0xFFFFFFFFu; }

        #pragma unroll 1
        for (int c = 0; c < NCHUNK; c++) {
            const int n0 = c * 16;
            const uint32_t bbase = bwarp + (uint32_t)(n0 * ROWB);

            uint32_t B[4][4];
            #pragma unroll
            for (int kt = 0; kt < 4; kt++)
                LDSM4(B[kt][0], B[kt][1], B[kt][2], B[kt][3], bbase + kt * 32);

            const float2 c0f = *reinterpret_cast<const float2*>(&snrm[n0 + 2 * t]);
            const float2 c1f = *reinterpret_cast<const float2*>(&snrm[n0 + 8 + 2 * t]);
            const float ck0x = c0f.x + OFFS, ck0y = c0f.y + OFFS;
            const float ck1x = c1f.x + OFFS, ck1y = c1f.y + OFFS;

            #pragma unroll
            for (int mt = 0; mt < 2; mt++) {
                float acc[2][4];
                #pragma unroll
                for (int nt = 0; nt < 2; nt++)
                    #pragma unroll
                    for (int q = 0; q < 4; q++) acc[nt][q] = 0.f;

                #pragma unroll
                for (int kt = 0; kt < 4; kt++) {
                    MMA16816(acc[0][0], acc[0][1], acc[0][2], acc[0][3],
                             Ah[mt][kt][0], Ah[mt][kt][1], Ah[mt][kt][2], Ah[mt][kt][3],
                             B[kt][0], B[kt][1]);
                    MMA16816(acc[1][0], acc[1][1], acc[1][2], acc[1][3],
                             Ah[mt][kt][0], Ah[mt][kt][1], Ah[mt][kt][2], Ah[mt][kt][3],
                             B[kt][2], B[kt][3]);
                }

                const int sA = 2 * mt, sB = 2 * mt + 1;
                #pragma unroll
                for (int nt = 0; nt < 2; nt++) {
                    const float cA = nt ? ck1x : ck0x;
                    const float cB = nt ? ck1y : ck0y;
                    const int colA = n0 + nt * 8 + 2 * t;
                    ins3p(K1[sA], K2[sA], K3[sA],
                          mkkey(acc[nt][0], cA, colA),
                          mkkey(acc[nt][1], cB, colA + 1));
                    ins3p(K1[sB], K2[sB], K3[sB],
                          mkkey(acc[nt][2], cA, colA),
                          mkkey(acc[nt][3], cB, colA + 1));
                }
            }
        }

        // Cross-lane merge (lanes 4g..4g+3 share the same 4 rows).
        #pragma unroll
        for (int xo = 1; xo <= 2; xo <<= 1) {
            #pragma unroll
            for (int s = 0; s < 4; s++) {
                uint32_t o1 = __shfl_xor_sync(0xFFFFFFFFu, K1[s], xo);
                uint32_t o2 = __shfl_xor_sync(0xFFFFFFFFu, K2[s], xo);
                uint32_t o3 = __shfl_xor_sync(0xFFFFFFFFu, K3[s], xo);
                ins3p(K1[s], K2[s], K3[s], o1, o2);
                ins3(K1[s], K2[s], K3[s], o3);
            }
        }

        // ---- Resolution: lane 4g+t owns slot t -> row (t>>1)*16+g+8*(t&1). ----
        const int my_row = row_base + (t >> 1) * 16 + g + 8 * (t & 1);
        const uint32_t key1 = K1[t], key2 = K2[t], key3 = K3[t];
        const int rk1 = (int)(key1 & 511u), rk2 = (int)(key2 & 511u);
        const float a1 = __uint_as_float(key1 & ~511u);
        const float a2 = __uint_as_float(key2 & ~511u);
        const float a3 = __uint_as_float(key3 & ~511u);
        int  kw = rk1;
        const bool need_full = (a3 - a1 < DELTA);
        const bool need_pair = !need_full && (a2 - a1 < DELTA);

        // Warp-cooperative full exact scans (rare; ~0.12% of tokens).
        unsigned fmask = __ballot_sync(0xFFFFFFFFu, need_full);
        while (fmask) {
            const int src = __ffs(fmask) - 1;
            fmask &= fmask - 1;
            const int stt = src & 3, sgg = src >> 2;
            const int srow = row_base + (stt >> 1) * 16 + sgg + 8 * (stt & 1);
            float4 zv[16];
            const float4* zp = reinterpret_cast<const float4*>(ze + (size_t)srow * DQ);
            #pragma unroll
            for (int i = 0; i < 16; i++) zv[i] = zp[i];
            float bd = 3.4e38f; int bk = 0;
            const int k0 = lane * 16;
            #pragma unroll 1
            for (int q = 0; q < 16; q++) {
                const int k = k0 + q;
                const float d = exact_dist(zv, cb + (size_t)k * DQ, snrm[k]);
                if (d < bd) { bd = d; bk = k; }
            }
            #pragma unroll
            for (int xo = 16; xo >= 1; xo >>= 1) {
                const float od = __shfl_xor_sync(0xFFFFFFFFu, bd, xo);
                const int   ok = __shfl_xor_sync(0xFFFFFFFFu, bk, xo);
                if (od < bd || (od == bd && ok < bk)) { bd = od; bk = ok; }
            }
            if (lane == src) kw = bk;
        }

        // Per-lane pairwise exact rescore (~5% of tokens).
        if (need_pair) {
            float4 zv[16];
            const float4* zp = reinterpret_cast<const float4*>(ze + (size_t)my_row * DQ);
            #pragma unroll
            for (int i = 0; i < 16; i++) zv[i] = zp[i];
            const float e1 = exact_dist(zv, cb + (size_t)rk1 * DQ, snrm[rk1]);
            const float e2 = exact_dist(zv, cb + (size_t)rk2 * DQ, snrm[rk2]);
            if (e2 < e1 || (e2 == e1 && rk2 < rk1)) kw = rk2;
        }

        // Coalesced gather (cb is L2-resident) + write, batched 4-deep.
        #pragma unroll 1
        for (int r0 = 0; r0 < 32; r0 += 4) {
            float2 v[4];
            #pragma unroll
            for (int j = 0; j < 4; j++) {
                const int r = r0 + j;
                const int mt = r >> 4, rr = (r >> 3) & 1, gg = r & 7;
                const int src_lane = 4 * gg + 2 * mt + rr;
                const int kk = __shfl_sync(0xFFFFFFFFu, kw, src_lane);
                v[j] = reinterpret_cast<const float2*>(cb + (size_t)kk * DQ)[lane];
            }
            #pragma unroll
            for (int j = 0; j < 4; j++)
                reinterpret_cast<float2*>(
                    out + (size_t)(row_base + r0 + j) * DQ)[lane] = v[j];
        }
    }
}

extern "C" void kernel_launch(void* const* d_in, const int* in_sizes, int n_in,
                              void* d_out, int out_size) {
    const float* ze = (const float*)d_in[0];
    const float* cb = (const float*)d_in[1];
    float* out = (float*)d_out;
    const int n_tokens = in_sizes[0] / DQ;
    const int n_tiles = n_tokens / MROWS;   // 2048

    prep_kernel<<<1, KC>>>(cb);
    cudaFuncSetAttribute(vq_main,
                         cudaFuncAttributeMaxDynamicSharedMemorySize, SMEM_TOTAL);
    vq_main<<<CTAS, THREADS, SMEM_TOTAL>>>(ze, cb, out, n_tiles);
}